// round 1
// baseline (speedup 1.0000x reference)
#include <cuda_runtime.h>
#include <cstdint>

#define N_NODES 100000
#define FT_IN   128
#define NHID    64
#define N_EDGES 1000000
#define PDIM    128            // [u(64) | v(64)] per node

// Scratch (allocation-free rule: __device__ globals)
__device__ float g_P[(size_t)N_NODES * PDIM];   // 51.2 MB — fits in L2
__device__ float g_Mt[FT_IN * PDIM];            // Mt[c][k] = M[k][c]
__device__ float g_beff[NHID];                  // b1 + W1a@b_enc + W1b@b_enc

// ---------------------------------------------------------------------------
// Prep: fold encoder+lin1 weights:  M[k][c] (k<64: W1a@W_enc, k>=64: W1b@W_enc)
// grid = 128 blocks (one input channel c each), 128 threads (one output k each)
// ---------------------------------------------------------------------------
__global__ void prep_kernel(const float* __restrict__ W_enc,
                            const float* __restrict__ W1,
                            const float* __restrict__ b_enc,
                            const float* __restrict__ b1) {
    int c = blockIdx.x;
    int k = threadIdx.x;
    __shared__ float we[NHID];                 // W_enc[j][c], j=0..63
    if (k < NHID) we[k] = W_enc[k * FT_IN + c];
    __syncthreads();

    const float* w1row = (k < NHID) ? (W1 + (size_t)k * (2 * NHID))
                                    : (W1 + (size_t)(k - NHID) * (2 * NHID) + NHID);
    float s = 0.f;
#pragma unroll 8
    for (int j = 0; j < NHID; j++) s = fmaf(w1row[j], we[j], s);
    g_Mt[c * PDIM + k] = s;

    if (c == 0 && k < NHID) {                  // effective bias
        const float* r = W1 + (size_t)k * (2 * NHID);
        float t = b1[k];
        for (int j = 0; j < NHID; j++) t = fmaf(r[j],        b_enc[j], t);
        for (int j = 0; j < NHID; j++) t = fmaf(r[NHID + j], b_enc[j], t);
        g_beff[k] = t;
    }
}

// ---------------------------------------------------------------------------
// GEMM: P[m][n] = sum_c seq[m][c] * Mt[c][n]   (M=100000, N=128, K=128)
// BM=128 rows/block, full N=128, BK=16. 256 threads, 8x8 register tile.
// Mt (64KB) staged in SMEM once per block; As staged transposed per K-tile.
// ---------------------------------------------------------------------------
#define BM 128
#define BK 16
#define AS_LD 132   // pad to dodge STS bank conflicts; multiple of 4 for float4

__global__ __launch_bounds__(256) void gemm_kernel(const float* __restrict__ seq) {
    extern __shared__ float sm[];
    float* Ms = sm;                      // [128][128] : Ms[c*128 + n]
    float* As = sm + 128 * 128;          // [BK][AS_LD]: As[c*AS_LD + m]

    const int tid = threadIdx.x;
    const int tx  = tid & 15;            // n-tile (16 tiles of 8)
    const int ty  = tid >> 4;            // m-tile (16 tiles of 8)
    const int rowBase = blockIdx.x * BM;

    // Stage full Mt into shared (coalesced float4)
    for (int idx = tid * 4; idx < 128 * 128; idx += 256 * 4)
        *(float4*)(Ms + idx) = *(const float4*)(g_Mt + idx);

    float acc[8][8];
#pragma unroll
    for (int i = 0; i < 8; i++)
#pragma unroll
        for (int j = 0; j < 8; j++) acc[i][j] = 0.f;

    const int lm = tid >> 2;             // 0..63
    const int lc = (tid & 3) * 4;        // 0,4,8,12

    __syncthreads();

    for (int kt = 0; kt < FT_IN / BK; kt++) {
        const int cBase = kt * BK;
        // load seq tile [128 rows][16 c], stored transposed As[c][m]
#pragma unroll
        for (int half = 0; half < 2; half++) {
            int m  = lm + half * 64;
            int gr = rowBase + m;
            if (gr > N_NODES - 1) gr = N_NODES - 1;   // clamp (stores guarded)
            float4 v = *(const float4*)(seq + (size_t)gr * FT_IN + cBase + lc);
            As[(lc + 0) * AS_LD + m] = v.x;
            As[(lc + 1) * AS_LD + m] = v.y;
            As[(lc + 2) * AS_LD + m] = v.z;
            As[(lc + 3) * AS_LD + m] = v.w;
        }
        __syncthreads();

#pragma unroll
        for (int c = 0; c < BK; c++) {
            float4 a0 = *(const float4*)(As + c * AS_LD + ty * 8);
            float4 a1 = *(const float4*)(As + c * AS_LD + ty * 8 + 4);
            const float* mrow = Ms + (cBase + c) * 128 + tx * 8;
            float4 b0 = *(const float4*)(mrow);
            float4 b1v = *(const float4*)(mrow + 4);
            float a[8] = {a0.x, a0.y, a0.z, a0.w, a1.x, a1.y, a1.z, a1.w};
            float b[8] = {b0.x, b0.y, b0.z, b0.w, b1v.x, b1v.y, b1v.z, b1v.w};
#pragma unroll
            for (int i = 0; i < 8; i++)
#pragma unroll
                for (int j = 0; j < 8; j++)
                    acc[i][j] = fmaf(a[i], b[j], acc[i][j]);
        }
        __syncthreads();
    }

    // write P
#pragma unroll
    for (int i = 0; i < 8; i++) {
        int row = rowBase + ty * 8 + i;
        if (row < N_NODES) {
            float* p = g_P + (size_t)row * PDIM + tx * 8;
            *(float4*)(p)     = make_float4(acc[i][0], acc[i][1], acc[i][2], acc[i][3]);
            *(float4*)(p + 4) = make_float4(acc[i][4], acc[i][5], acc[i][6], acc[i][7]);
        }
    }
}

// ---------------------------------------------------------------------------
// Edge kernel: warp per edge. u = P[row][0:64], v = P[col][64:128]
// out[e] = sum_k relu(u+v+beff)[k] * w2[k] + b2
// Coalesced 256B row-segment loads (float2/lane), L2-resident P.
// ---------------------------------------------------------------------------
__global__ __launch_bounds__(256) void edge_kernel(const int* __restrict__ row,
                                                   const int* __restrict__ col,
                                                   const float* __restrict__ W2,
                                                   const float* __restrict__ b2,
                                                   float* __restrict__ out) {
    const int warp = (blockIdx.x * blockDim.x + threadIdx.x) >> 5;
    const int lane = threadIdx.x & 31;
    if (warp >= N_EDGES) return;

    const int r = row[warp];             // broadcast load
    const int c = col[warp];

    const float2 u  = *(const float2*)(g_P + (size_t)r * PDIM + 2 * lane);
    const float2 v  = *(const float2*)(g_P + (size_t)c * PDIM + NHID + 2 * lane);
    const float2 be = *(const float2*)(g_beff + 2 * lane);
    const float2 w2 = *(const float2*)(W2 + 2 * lane);

    const float h0 = fmaxf(u.x + v.x + be.x, 0.f);
    const float h1 = fmaxf(u.y + v.y + be.y, 0.f);
    float p = fmaf(h0, w2.x, h1 * w2.y);

#pragma unroll
    for (int o = 16; o; o >>= 1) p += __shfl_down_sync(0xffffffffu, p, o);

    if (lane == 0) out[warp] = p + b2[0];
}

// ---------------------------------------------------------------------------
extern "C" void kernel_launch(void* const* d_in, const int* in_sizes, int n_in,
                              void* d_out, int out_size) {
    const float* seq   = (const float*)d_in[0];
    const float* W_enc = (const float*)d_in[1];
    const float* b_enc = (const float*)d_in[2];
    const float* W1    = (const float*)d_in[3];
    const float* b1    = (const float*)d_in[4];
    const float* W2    = (const float*)d_in[5];
    const float* b2    = (const float*)d_in[6];
    const int*   row   = (const int*)d_in[7];
    const int*   col   = (const int*)d_in[8];
    float* out = (float*)d_out;

    // prep: fold weights
    prep_kernel<<<FT_IN, 128>>>(W_enc, W1, b_enc, b1);

    // GEMM: P = seq @ M^T
    const int smem = (128 * 128 + BK * AS_LD) * sizeof(float);   // ~73.7 KB
    cudaFuncSetAttribute(gemm_kernel, cudaFuncAttributeMaxDynamicSharedMemorySize, smem);
    gemm_kernel<<<(N_NODES + BM - 1) / BM, 256, smem>>>(seq);

    // per-edge decode: 8 warps/block, warp per edge
    edge_kernel<<<(N_EDGES * 32 + 255) / 256, 256>>>(row, col, W2, b2, out);
}

// round 3
// speedup vs baseline: 1.1908x; 1.1908x over previous
#include <cuda_runtime.h>
#include <cuda_bf16.h>
#include <cstdint>

#define N_NODES 100000
#define FT_IN   128
#define NHID    64
#define N_EDGES 1000000
#define PDIM    128
#define BSTR    136            // padded k-stride (bf16 elements) -> 272 B rows

// ---------------------------------------------------------------------------
// Device scratch (allocation-free rule)
// ---------------------------------------------------------------------------
__device__ float g_P[(size_t)N_NODES * PDIM];                 // 51.2 MB, L2-resident
__device__ __align__(16) __nv_bfloat16 g_Bhi[PDIM * BSTR];    // B[n][k] hi, padded
__device__ __align__(16) __nv_bfloat16 g_Blo[PDIM * BSTR];    // B[n][k] lo
__device__ float g_beff[NHID];

// ---------------------------------------------------------------------------
// PTX helpers (compute_100-legal: ldmatrix + mma.sync only)
// ---------------------------------------------------------------------------
__device__ __forceinline__ uint32_t smem_u32(const void* p) {
    uint32_t a;
    asm("{ .reg .u64 t; cvta.to.shared.u64 t, %1; cvt.u32.u64 %0, t; }" : "=r"(a) : "l"(p));
    return a;
}
__device__ __forceinline__ void ldsm_x4(uint32_t* r, uint32_t a) {
    asm volatile("ldmatrix.sync.aligned.m8n8.x4.shared.b16 {%0,%1,%2,%3}, [%4];"
                 : "=r"(r[0]), "=r"(r[1]), "=r"(r[2]), "=r"(r[3]) : "r"(a));
}
__device__ __forceinline__ void ldsm_x2(uint32_t* r, uint32_t a) {
    asm volatile("ldmatrix.sync.aligned.m8n8.x2.shared.b16 {%0,%1}, [%2];"
                 : "=r"(r[0]), "=r"(r[1]) : "r"(a));
}
__device__ __forceinline__ void mma_bf16(float* d, const uint32_t* a, const uint32_t* b) {
    asm volatile("mma.sync.aligned.m16n8k16.row.col.f32.bf16.bf16.f32 "
                 "{%0,%1,%2,%3}, {%4,%5,%6,%7}, {%8,%9}, {%0,%1,%2,%3};"
                 : "+f"(d[0]), "+f"(d[1]), "+f"(d[2]), "+f"(d[3])
                 : "r"(a[0]), "r"(a[1]), "r"(a[2]), "r"(a[3]), "r"(b[0]), "r"(b[1]));
}
__device__ __forceinline__ uint32_t pack_bf16x2(float a, float b) {
    uint32_t r;
    asm("cvt.rn.bf16x2.f32 %0, %2, %1;" : "=r"(r) : "f"(a), "f"(b));
    return r;
}

// ---------------------------------------------------------------------------
// Prep: B[n][c] = sum_j W1row(n)[j] * W_enc[j][c]  (n<64: W1a row; n>=64: W1b row)
// emitted as bf16 hi/lo in padded [n][k] layout. grid = 128 (n) x 128 thr (c).
// ---------------------------------------------------------------------------
__global__ __launch_bounds__(128) void prep_kernel(const float* __restrict__ W_enc,
                                                   const float* __restrict__ W1,
                                                   const float* __restrict__ b_enc,
                                                   const float* __restrict__ b1) {
    const int n = blockIdx.x;
    const int c = threadIdx.x;
    __shared__ float ws[NHID];
    if (c < NHID) {
        const float* w1row = (n < NHID) ? (W1 + (size_t)n * (2 * NHID))
                                        : (W1 + (size_t)(n - NHID) * (2 * NHID) + NHID);
        ws[c] = w1row[c];
    }
    __syncthreads();

    float s = 0.f;
#pragma unroll 8
    for (int j = 0; j < NHID; j++) s = fmaf(ws[j], W_enc[j * FT_IN + c], s);

    __nv_bfloat16 hi = __float2bfloat16_rn(s);
    g_Bhi[n * BSTR + c] = hi;
    g_Blo[n * BSTR + c] = __float2bfloat16_rn(s - __bfloat162float(hi));

    if (n == 0 && c < NHID) {
        const float* r = W1 + (size_t)c * (2 * NHID);
        float t = b1[c];
        for (int j = 0; j < NHID; j++) t = fmaf(r[j],        b_enc[j], t);
        for (int j = 0; j < NHID; j++) t = fmaf(r[NHID + j], b_enc[j], t);
        g_beff[c] = t;
    }
}

// ---------------------------------------------------------------------------
// GEMM: P[100000,128] = seq @ B^T via mma.sync bf16 hi/lo (3 combos).
// CTA: 128 rows x 128 cols, 8 warps (4M x 2N), warp tile 32x64.
// ---------------------------------------------------------------------------
#define SM_AHI 0
#define SM_ALO 34816
#define SM_BHI 69632
#define SM_BLO 104448
#define SM_TOTAL 139264

__global__ __launch_bounds__(256) void gemm_kernel(const float* __restrict__ seq) {
    extern __shared__ unsigned char sm[];
    const uint32_t sb = smem_u32(sm);
    const int tid  = threadIdx.x;
    const int rowBase = blockIdx.x * 128;

    // Stage B hi/lo (linear 16B copies of padded images)
    {
        const uint4* shi = (const uint4*)g_Bhi;
        const uint4* slo = (const uint4*)g_Blo;
        uint4* dhi = (uint4*)(sm + SM_BHI);
        uint4* dlo = (uint4*)(sm + SM_BLO);
        for (int i = tid; i < PDIM * BSTR * 2 / 16; i += 256) { dhi[i] = shi[i]; dlo[i] = slo[i]; }
    }

    // Stage A: fp32 seq rows -> bf16 hi/lo, padded [m][k] stride 272B
    {
        const int rowm = tid >> 1;
        const int half = tid & 1;
        int g = rowBase + rowm; if (g > N_NODES - 1) g = N_NODES - 1;
        const float* src = seq + (size_t)g * FT_IN + half * 64;
        const int dbase = rowm * (BSTR * 2) + half * 128;
#pragma unroll
        for (int i = 0; i < 8; i++) {
            float4 v0 = *(const float4*)(src + i * 8);
            float4 v1 = *(const float4*)(src + i * 8 + 4);
            float f[8] = {v0.x, v0.y, v0.z, v0.w, v1.x, v1.y, v1.z, v1.w};
            uint32_t hi[4], lo[4];
#pragma unroll
            for (int p = 0; p < 4; p++) {
                float a = f[2 * p], b = f[2 * p + 1];
                float ah = __bfloat162float(__float2bfloat16_rn(a));
                float bh = __bfloat162float(__float2bfloat16_rn(b));
                hi[p] = pack_bf16x2(ah, bh);
                lo[p] = pack_bf16x2(a - ah, b - bh);
            }
            *(uint4*)(sm + SM_AHI + dbase + i * 16) = make_uint4(hi[0], hi[1], hi[2], hi[3]);
            *(uint4*)(sm + SM_ALO + dbase + i * 16) = make_uint4(lo[0], lo[1], lo[2], lo[3]);
        }
    }
    __syncthreads();

    const int warp = tid >> 5, lane = tid & 31;
    const int wM = warp & 3, wN = warp >> 2;     // 4 x 2 warp grid

    float acc[2][8][4];
#pragma unroll
    for (int mt = 0; mt < 2; mt++)
#pragma unroll
        for (int nt = 0; nt < 8; nt++)
#pragma unroll
            for (int q = 0; q < 4; q++) acc[mt][nt][q] = 0.f;

    // ldmatrix lane addressing
    const uint32_t aAddr = sb + SM_AHI + (uint32_t)((wM * 32 + (lane & 15)) * (BSTR * 2)
                                                    + ((lane >> 4) << 3) * 2);
    const uint32_t bAddr = sb + SM_BHI + (uint32_t)((wN * 64 + (lane & 7)) * (BSTR * 2)
                                                    + (((lane >> 3) & 1) << 3) * 2);

#pragma unroll
    for (int k0 = 0; k0 < FT_IN; k0 += 16) {
        uint32_t ah[2][4], al[2][4], bh[8][2], bl[8][2];
#pragma unroll
        for (int mt = 0; mt < 2; mt++) {
            uint32_t a = aAddr + mt * 16 * (BSTR * 2) + k0 * 2;
            ldsm_x4(ah[mt], a);
            ldsm_x4(al[mt], a + (SM_ALO - SM_AHI));
        }
#pragma unroll
        for (int nt = 0; nt < 8; nt++) {
            uint32_t b = bAddr + nt * 8 * (BSTR * 2) + k0 * 2;
            ldsm_x2(bh[nt], b);
            ldsm_x2(bl[nt], b + (SM_BLO - SM_BHI));
        }
#pragma unroll
        for (int mt = 0; mt < 2; mt++)
#pragma unroll
            for (int nt = 0; nt < 8; nt++) {
                mma_bf16(acc[mt][nt], ah[mt], bh[nt]);   // hi*hi
                mma_bf16(acc[mt][nt], ah[mt], bl[nt]);   // hi*lo
                mma_bf16(acc[mt][nt], al[mt], bh[nt]);   // lo*hi
            }
    }

    // Epilogue: acc -> g_P
    const int r0 = rowBase + wM * 32 + (lane >> 2);
    const int cB = wN * 64 + (lane & 3) * 2;
#pragma unroll
    for (int mt = 0; mt < 2; mt++) {
        const int ra = r0 + mt * 16;
#pragma unroll
        for (int nt = 0; nt < 8; nt++) {
            const int col = cB + nt * 8;
            if (ra < N_NODES)
                *(float2*)(g_P + (size_t)ra * PDIM + col)
                    = make_float2(acc[mt][nt][0], acc[mt][nt][1]);
            if (ra + 8 < N_NODES)
                *(float2*)(g_P + (size_t)(ra + 8) * PDIM + col)
                    = make_float2(acc[mt][nt][2], acc[mt][nt][3]);
        }
    }
}

// ---------------------------------------------------------------------------
// Edge kernel: warp per edge. u = P[row][0:64], v = P[col][64:128]
// ---------------------------------------------------------------------------
__global__ __launch_bounds__(256) void edge_kernel(const int* __restrict__ row,
                                                   const int* __restrict__ col,
                                                   const float* __restrict__ W2,
                                                   const float* __restrict__ b2,
                                                   float* __restrict__ out) {
    const int warp = (blockIdx.x * blockDim.x + threadIdx.x) >> 5;
    const int lane = threadIdx.x & 31;
    if (warp >= N_EDGES) return;

    const int r = row[warp];
    const int c = col[warp];

    const float2 u  = *(const float2*)(g_P + (size_t)r * PDIM + 2 * lane);
    const float2 v  = *(const float2*)(g_P + (size_t)c * PDIM + NHID + 2 * lane);
    const float2 be = *(const float2*)(g_beff + 2 * lane);
    const float2 w2 = *(const float2*)(W2 + 2 * lane);

    const float h0 = fmaxf(u.x + v.x + be.x, 0.f);
    const float h1 = fmaxf(u.y + v.y + be.y, 0.f);
    float p = fmaf(h0, w2.x, h1 * w2.y);

#pragma unroll
    for (int o = 16; o; o >>= 1) p += __shfl_down_sync(0xffffffffu, p, o);

    if (lane == 0) out[warp] = p + b2[0];
}

// ---------------------------------------------------------------------------
extern "C" void kernel_launch(void* const* d_in, const int* in_sizes, int n_in,
                              void* d_out, int out_size) {
    const float* seq   = (const float*)d_in[0];
    const float* W_enc = (const float*)d_in[1];
    const float* b_enc = (const float*)d_in[2];
    const float* W1    = (const float*)d_in[3];
    const float* b1    = (const float*)d_in[4];
    const float* W2    = (const float*)d_in[5];
    const float* b2    = (const float*)d_in[6];
    const int*   rowi  = (const int*)d_in[7];
    const int*   coli  = (const int*)d_in[8];
    float* out = (float*)d_out;

    prep_kernel<<<128, 128>>>(W_enc, W1, b_enc, b1);

    cudaFuncSetAttribute(gemm_kernel, cudaFuncAttributeMaxDynamicSharedMemorySize, SM_TOTAL);
    gemm_kernel<<<(N_NODES + 127) / 128, 256, SM_TOTAL>>>(seq);

    edge_kernel<<<(N_EDGES * 32 + 255) / 256, 256>>>(rowi, coli, W2, b2, out);
}

// round 4
// speedup vs baseline: 1.3356x; 1.1216x over previous
#include <cuda_runtime.h>
#include <cuda_fp16.h>
#include <cstdint>

#define N_NODES 100000
#define FT_IN   128
#define NHID    64
#define N_EDGES 1000000
#define PDIM    128
#define KSTR    136            // padded k-stride in halves -> 272 B rows

// ---------------------------------------------------------------------------
// Device scratch
// ---------------------------------------------------------------------------
__device__ __half g_Ph[(size_t)N_NODES * PDIM];          // 25.6 MB, L2-resident
__device__ __align__(16) __half g_Bhi[PDIM * KSTR];      // B[n][k] hi (padded)
__device__ __align__(16) __half g_Blo[PDIM * KSTR];      // B[n][k] lo
__device__ float g_beff[NHID];

// ---------------------------------------------------------------------------
// PTX helpers (compute_100-legal)
// ---------------------------------------------------------------------------
__device__ __forceinline__ uint32_t smem_u32(const void* p) {
    uint32_t a;
    asm("{ .reg .u64 t; cvta.to.shared.u64 t, %1; cvt.u32.u64 %0, t; }" : "=r"(a) : "l"(p));
    return a;
}
__device__ __forceinline__ void ldsm_x4(uint32_t* r, uint32_t a) {
    asm volatile("ldmatrix.sync.aligned.m8n8.x4.shared.b16 {%0,%1,%2,%3}, [%4];"
                 : "=r"(r[0]), "=r"(r[1]), "=r"(r[2]), "=r"(r[3]) : "r"(a));
}
__device__ __forceinline__ void ldsm_x2(uint32_t* r, uint32_t a) {
    asm volatile("ldmatrix.sync.aligned.m8n8.x2.shared.b16 {%0,%1}, [%2];"
                 : "=r"(r[0]), "=r"(r[1]) : "r"(a));
}
__device__ __forceinline__ void mma_f16(float* d, const uint32_t* a, const uint32_t* b) {
    asm volatile("mma.sync.aligned.m16n8k16.row.col.f32.f16.f16.f32 "
                 "{%0,%1,%2,%3}, {%4,%5,%6,%7}, {%8,%9}, {%0,%1,%2,%3};"
                 : "+f"(d[0]), "+f"(d[1]), "+f"(d[2]), "+f"(d[3])
                 : "r"(a[0]), "r"(a[1]), "r"(a[2]), "r"(a[3]), "r"(b[0]), "r"(b[1]));
}

// ---------------------------------------------------------------------------
// Prep: B[n][c] = sum_j W1row(n)[j] * W_enc[j][c]; fp16 hi/lo, padded [n][k].
// ---------------------------------------------------------------------------
__global__ __launch_bounds__(128) void prep_kernel(const float* __restrict__ W_enc,
                                                   const float* __restrict__ W1,
                                                   const float* __restrict__ b_enc,
                                                   const float* __restrict__ b1) {
    const int n = blockIdx.x;
    const int c = threadIdx.x;
    __shared__ float ws[NHID];
    if (c < NHID) {
        const float* w1row = (n < NHID) ? (W1 + (size_t)n * (2 * NHID))
                                        : (W1 + (size_t)(n - NHID) * (2 * NHID) + NHID);
        ws[c] = w1row[c];
    }
    __syncthreads();

    float s = 0.f;
#pragma unroll
    for (int j = 0; j < NHID; j++) s = fmaf(ws[j], W_enc[j * FT_IN + c], s);

    const __half hi = __float2half_rn(s);
    g_Bhi[n * KSTR + c] = hi;
    g_Blo[n * KSTR + c] = __float2half_rn(s - __half2float(hi));

    if (n == 0 && c < NHID) {
        const float* r = W1 + (size_t)c * (2 * NHID);
        float t = b1[c];
#pragma unroll
        for (int j = 0; j < NHID; j++) t = fmaf(r[j],        b_enc[j], t);
#pragma unroll
        for (int j = 0; j < NHID; j++) t = fmaf(r[NHID + j], b_enc[j], t);
        g_beff[c] = t;
    }
}

// ---------------------------------------------------------------------------
// GEMM: P[100000,128] = seq @ B^T via mma.sync fp16 hi/lo (3 combos).
// CTA: 64 rows x 128 cols, 8 warps (2M x 4N), warp tile 32x32. 2 CTAs/SM.
// ---------------------------------------------------------------------------
#define SM_AHI 0
#define SM_ALO 17408
#define SM_BHI 34816
#define SM_BLO 69632
#define SM_TOTAL 104448
#define EPI_STR 272            // epilogue smem tile row stride (bytes)

__global__ __launch_bounds__(256, 2) void gemm_kernel(const float* __restrict__ seq) {
    extern __shared__ unsigned char sm[];
    const uint32_t sb = smem_u32(sm);
    const int tid = threadIdx.x;
    const int rowBase = blockIdx.x * 64;

    // Stage B hi/lo (linear copy of padded images; L2-hot broadcast data)
    {
        const uint4* shi = (const uint4*)g_Bhi;
        const uint4* slo = (const uint4*)g_Blo;
        uint4* dhi = (uint4*)(sm + SM_BHI);
        uint4* dlo = (uint4*)(sm + SM_BLO);
#pragma unroll 2
        for (int i = tid; i < PDIM * KSTR * 2 / 16; i += 256) { dhi[i] = shi[i]; dlo[i] = slo[i]; }
    }

    // Stage A: 64 rows x 128 fp32 -> fp16 hi/lo, 4 threads/row (32 floats each)
    {
        const int rowm = tid >> 2;            // 0..63
        const int q    = tid & 3;             // 32-float quarter
        int g = rowBase + rowm; if (g > N_NODES - 1) g = N_NODES - 1;
        const float* src = seq + (size_t)g * FT_IN + q * 32;
        const int db = rowm * (KSTR * 2) + q * 64;    // bytes
#pragma unroll
        for (int i = 0; i < 4; i++) {         // 4 groups of 8 floats
            float4 v0 = *(const float4*)(src + i * 8);
            float4 v1 = *(const float4*)(src + i * 8 + 4);
            float f[8] = {v0.x, v0.y, v0.z, v0.w, v1.x, v1.y, v1.z, v1.w};
            uint32_t hi[4], lo[4];
#pragma unroll
            for (int p = 0; p < 4; p++) {
                float a = f[2 * p], b = f[2 * p + 1];
                __half2 h = __floats2half2_rn(a, b);
                float2 hf = __half22float2(h);
                __half2 l = __floats2half2_rn(a - hf.x, b - hf.y);
                hi[p] = *(uint32_t*)&h;
                lo[p] = *(uint32_t*)&l;
            }
            *(uint4*)(sm + SM_AHI + db + i * 16) = make_uint4(hi[0], hi[1], hi[2], hi[3]);
            *(uint4*)(sm + SM_ALO + db + i * 16) = make_uint4(lo[0], lo[1], lo[2], lo[3]);
        }
    }
    __syncthreads();

    const int warp = tid >> 5, lane = tid & 31;
    const int wM = warp & 1, wN = warp >> 1;      // 2 x 4 warp grid, tile 32x32

    float acc[2][4][4];
#pragma unroll
    for (int mt = 0; mt < 2; mt++)
#pragma unroll
        for (int nt = 0; nt < 4; nt++)
#pragma unroll
            for (int q = 0; q < 4; q++) acc[mt][nt][q] = 0.f;

    const uint32_t aAddr = sb + SM_AHI + (uint32_t)((wM * 32 + (lane & 15)) * (KSTR * 2)
                                                    + ((lane >> 4) << 3) * 2);
    const uint32_t bAddr = sb + SM_BHI + (uint32_t)((wN * 32 + (lane & 7)) * (KSTR * 2)
                                                    + (((lane >> 3) & 1) << 3) * 2);

#pragma unroll
    for (int k0 = 0; k0 < FT_IN; k0 += 16) {
        uint32_t ah[2][4], al[2][4], bh[4][2], bl[4][2];
#pragma unroll
        for (int mt = 0; mt < 2; mt++) {
            uint32_t a = aAddr + mt * 16 * (KSTR * 2) + k0 * 2;
            ldsm_x4(ah[mt], a);
            ldsm_x4(al[mt], a + (SM_ALO - SM_AHI));
        }
#pragma unroll
        for (int nt = 0; nt < 4; nt++) {
            uint32_t b = bAddr + nt * 8 * (KSTR * 2) + k0 * 2;
            ldsm_x2(bh[nt], b);
            ldsm_x2(bl[nt], b + (SM_BLO - SM_BHI));
        }
#pragma unroll
        for (int mt = 0; mt < 2; mt++)
#pragma unroll
            for (int nt = 0; nt < 4; nt++) {
                mma_f16(acc[mt][nt], ah[mt], bh[nt]);
                mma_f16(acc[mt][nt], ah[mt], bl[nt]);
                mma_f16(acc[mt][nt], al[mt], bh[nt]);
            }
    }
    __syncthreads();      // A region reused as epilogue tile

    // Epilogue: fp32 acc -> fp16, stage in smem [64][128] halves (stride 272B)
    {
        unsigned char* tile = sm;   // reuse SM_AHI region (16.4KB < 17.4KB)
        const int r0 = wM * 32 + (lane >> 2);
        const int c0 = wN * 32 + (lane & 3) * 2;
#pragma unroll
        for (int mt = 0; mt < 2; mt++)
#pragma unroll
            for (int nt = 0; nt < 4; nt++) {
                const int col = c0 + nt * 8;
                __half2 lo2 = __floats2half2_rn(acc[mt][nt][0], acc[mt][nt][1]);
                __half2 hi2 = __floats2half2_rn(acc[mt][nt][2], acc[mt][nt][3]);
                *(__half2*)(tile + (r0 + mt * 16)     * EPI_STR + col * 2) = lo2;
                *(__half2*)(tile + (r0 + mt * 16 + 8) * EPI_STR + col * 2) = hi2;
            }
    }
    __syncthreads();

    // Coalesced copy to g_Ph: 64 rows x 256B
    {
        const int rowm = tid >> 2;
        const int seg  = tid & 3;
        const int grow = rowBase + rowm;
        if (grow < N_NODES) {
            const uint4* s4 = (const uint4*)(sm + rowm * EPI_STR + seg * 64);
            uint4* d4 = (uint4*)((unsigned char*)g_Ph + (size_t)grow * 256 + seg * 64);
#pragma unroll
            for (int i = 0; i < 4; i++) d4[i] = s4[i];
        }
    }
}

// ---------------------------------------------------------------------------
// Edge kernel: warp per edge. fp16 P: u,v = 128B coalesced each.
// ---------------------------------------------------------------------------
__global__ __launch_bounds__(256) void edge_kernel(const int* __restrict__ row,
                                                   const int* __restrict__ col,
                                                   const float* __restrict__ W2,
                                                   const float* __restrict__ b2,
                                                   float* __restrict__ out) {
    const int warp = (blockIdx.x * blockDim.x + threadIdx.x) >> 5;
    const int lane = threadIdx.x & 31;
    if (warp >= N_EDGES) return;

    const int r = row[warp];
    const int c = col[warp];

    const __half2 uh = *((const __half2*)(g_Ph + (size_t)r * PDIM) + lane);
    const __half2 vh = *((const __half2*)(g_Ph + (size_t)c * PDIM + NHID) + lane);
    const float2 u  = __half22float2(uh);
    const float2 v  = __half22float2(vh);
    const float2 be = *(const float2*)(g_beff + 2 * lane);
    const float2 w2 = *(const float2*)(W2 + 2 * lane);

    const float h0 = fmaxf(u.x + v.x + be.x, 0.f);
    const float h1 = fmaxf(u.y + v.y + be.y, 0.f);
    float p = fmaf(h0, w2.x, h1 * w2.y);

#pragma unroll
    for (int o = 16; o; o >>= 1) p += __shfl_down_sync(0xffffffffu, p, o);

    if (lane == 0) out[warp] = p + b2[0];
}

// ---------------------------------------------------------------------------
extern "C" void kernel_launch(void* const* d_in, const int* in_sizes, int n_in,
                              void* d_out, int out_size) {
    const float* seq   = (const float*)d_in[0];
    const float* W_enc = (const float*)d_in[1];
    const float* b_enc = (const float*)d_in[2];
    const float* W1    = (const float*)d_in[3];
    const float* b1    = (const float*)d_in[4];
    const float* W2    = (const float*)d_in[5];
    const float* b2    = (const float*)d_in[6];
    const int*   rowi  = (const int*)d_in[7];
    const int*   coli  = (const int*)d_in[8];
    float* out = (float*)d_out;

    prep_kernel<<<128, 128>>>(W_enc, W1, b_enc, b1);

    cudaFuncSetAttribute(gemm_kernel, cudaFuncAttributeMaxDynamicSharedMemorySize, SM_TOTAL);
    gemm_kernel<<<(N_NODES + 63) / 64, 256, SM_TOTAL>>>(seq);

    edge_kernel<<<(N_EDGES * 32 + 255) / 256, 256>>>(rowi, coli, W2, b2, out);
}

// round 5
// speedup vs baseline: 2.4821x; 1.8584x over previous
#include <cuda_runtime.h>
#include <cuda_fp16.h>
#include <cstdint>

#define N_NODES 100000
#define FT_IN   128
#define NHID    64
#define N_EDGES 1000000
#define PDIM    128
#define KSTR    136            // padded k-stride in halves -> 272 B rows

// ---------------------------------------------------------------------------
// Device scratch
// ---------------------------------------------------------------------------
__device__ __half g_Ph[(size_t)N_NODES * PDIM];          // 25.6 MB, L2-resident
__device__ __align__(16) __half g_Bh[PDIM * KSTR];       // B[n][k] fp16 (padded)
__device__ float g_beff[NHID];

// ---------------------------------------------------------------------------
// PTX helpers (compute_100-legal)
// ---------------------------------------------------------------------------
__device__ __forceinline__ uint32_t smem_u32(const void* p) {
    uint32_t a;
    asm("{ .reg .u64 t; cvta.to.shared.u64 t, %1; cvt.u32.u64 %0, t; }" : "=r"(a) : "l"(p));
    return a;
}
__device__ __forceinline__ void ldsm_x4(uint32_t* r, uint32_t a) {
    asm volatile("ldmatrix.sync.aligned.m8n8.x4.shared.b16 {%0,%1,%2,%3}, [%4];"
                 : "=r"(r[0]), "=r"(r[1]), "=r"(r[2]), "=r"(r[3]) : "r"(a));
}
__device__ __forceinline__ void ldsm_x2(uint32_t* r, uint32_t a) {
    asm volatile("ldmatrix.sync.aligned.m8n8.x2.shared.b16 {%0,%1}, [%2];"
                 : "=r"(r[0]), "=r"(r[1]) : "r"(a));
}
__device__ __forceinline__ void mma_f16(float* d, const uint32_t* a, const uint32_t* b) {
    asm volatile("mma.sync.aligned.m16n8k16.row.col.f32.f16.f16.f32 "
                 "{%0,%1,%2,%3}, {%4,%5,%6,%7}, {%8,%9}, {%0,%1,%2,%3};"
                 : "+f"(d[0]), "+f"(d[1]), "+f"(d[2]), "+f"(d[3])
                 : "r"(a[0]), "r"(a[1]), "r"(a[2]), "r"(a[3]), "r"(b[0]), "r"(b[1]));
}

// ---------------------------------------------------------------------------
// Prep: B[n][c] = sum_j W1row(n)[j] * W_enc[j][c]; fp16, padded [n][k].
// ---------------------------------------------------------------------------
__global__ __launch_bounds__(128) void prep_kernel(const float* __restrict__ W_enc,
                                                   const float* __restrict__ W1,
                                                   const float* __restrict__ b_enc,
                                                   const float* __restrict__ b1) {
    const int n = blockIdx.x;
    const int c = threadIdx.x;
    __shared__ float ws[NHID];
    if (c < NHID) {
        const float* w1row = (n < NHID) ? (W1 + (size_t)n * (2 * NHID))
                                        : (W1 + (size_t)(n - NHID) * (2 * NHID) + NHID);
        ws[c] = w1row[c];
    }
    __syncthreads();

    float s = 0.f;
#pragma unroll
    for (int j = 0; j < NHID; j++) s = fmaf(ws[j], W_enc[j * FT_IN + c], s);

    g_Bh[n * KSTR + c] = __float2half_rn(s);

    if (n == 0 && c < NHID) {
        const float* r = W1 + (size_t)c * (2 * NHID);
        float t = b1[c];
#pragma unroll
        for (int j = 0; j < NHID; j++) t = fmaf(r[j],        b_enc[j], t);
#pragma unroll
        for (int j = 0; j < NHID; j++) t = fmaf(r[NHID + j], b_enc[j], t);
        g_beff[c] = t;
    }
}

// ---------------------------------------------------------------------------
// GEMM: P[100000,128] = seq @ B^T via mma.sync fp16, A split hi/lo (2 combos).
// CTA: 64 rows x 128 cols, 8 warps (2M x 4N), warp tile 32x32. ~68KB smem.
// ---------------------------------------------------------------------------
#define SM_AHI 0
#define SM_ALO 17408
#define SM_BHI 34816
#define SM_TOTAL 69632
#define EPI_STR 272            // epilogue smem tile row stride (bytes)

__global__ __launch_bounds__(256, 2) void gemm_kernel(const float* __restrict__ seq) {
    extern __shared__ unsigned char sm[];
    const uint32_t sb = smem_u32(sm);
    const int tid = threadIdx.x;
    const int rowBase = blockIdx.x * 64;

    // Stage B (linear copy of padded image; L2-hot broadcast data)
    {
        const uint4* s4 = (const uint4*)g_Bh;
        uint4* d4 = (uint4*)(sm + SM_BHI);
#pragma unroll 3
        for (int i = tid; i < PDIM * KSTR * 2 / 16; i += 256) d4[i] = s4[i];
    }

    // Stage A: 64 rows x 128 fp32 -> fp16 hi/lo, 4 threads/row (32 floats each)
    {
        const int rowm = tid >> 2;            // 0..63
        const int q    = tid & 3;             // 32-float quarter
        int g = rowBase + rowm; if (g > N_NODES - 1) g = N_NODES - 1;
        const float* src = seq + (size_t)g * FT_IN + q * 32;
        const int db = rowm * (KSTR * 2) + q * 64;    // bytes
#pragma unroll
        for (int i = 0; i < 4; i++) {         // 4 groups of 8 floats
            float4 v0 = *(const float4*)(src + i * 8);
            float4 v1 = *(const float4*)(src + i * 8 + 4);
            float f[8] = {v0.x, v0.y, v0.z, v0.w, v1.x, v1.y, v1.z, v1.w};
            uint32_t hi[4], lo[4];
#pragma unroll
            for (int p = 0; p < 4; p++) {
                float a = f[2 * p], b = f[2 * p + 1];
                __half2 h = __floats2half2_rn(a, b);
                float2 hf = __half22float2(h);
                __half2 l = __floats2half2_rn(a - hf.x, b - hf.y);
                hi[p] = *(uint32_t*)&h;
                lo[p] = *(uint32_t*)&l;
            }
            *(uint4*)(sm + SM_AHI + db + i * 16) = make_uint4(hi[0], hi[1], hi[2], hi[3]);
            *(uint4*)(sm + SM_ALO + db + i * 16) = make_uint4(lo[0], lo[1], lo[2], lo[3]);
        }
    }
    __syncthreads();

    const int warp = tid >> 5, lane = tid & 31;
    const int wM = warp & 1, wN = warp >> 1;      // 2 x 4 warp grid, tile 32x32

    float acc[2][4][4];
#pragma unroll
    for (int mt = 0; mt < 2; mt++)
#pragma unroll
        for (int nt = 0; nt < 4; nt++)
#pragma unroll
            for (int q = 0; q < 4; q++) acc[mt][nt][q] = 0.f;

    const uint32_t aAddr = sb + SM_AHI + (uint32_t)((wM * 32 + (lane & 15)) * (KSTR * 2)
                                                    + ((lane >> 4) << 3) * 2);
    const uint32_t bAddr = sb + SM_BHI + (uint32_t)((wN * 32 + (lane & 7)) * (KSTR * 2)
                                                    + (((lane >> 3) & 1) << 3) * 2);

#pragma unroll
    for (int k0 = 0; k0 < FT_IN; k0 += 16) {
        uint32_t ah[2][4], al[2][4], bh[4][2];
#pragma unroll
        for (int mt = 0; mt < 2; mt++) {
            uint32_t a = aAddr + mt * 16 * (KSTR * 2) + k0 * 2;
            ldsm_x4(ah[mt], a);
            ldsm_x4(al[mt], a + (SM_ALO - SM_AHI));
        }
#pragma unroll
        for (int nt = 0; nt < 4; nt++)
            ldsm_x2(bh[nt], bAddr + nt * 8 * (KSTR * 2) + k0 * 2);
#pragma unroll
        for (int mt = 0; mt < 2; mt++)
#pragma unroll
            for (int nt = 0; nt < 4; nt++) {
                mma_f16(acc[mt][nt], ah[mt], bh[nt]);   // Ahi * B
                mma_f16(acc[mt][nt], al[mt], bh[nt]);   // Alo * B
            }
    }
    __syncthreads();      // A region reused as epilogue tile

    // Epilogue: fp32 acc -> fp16, stage in smem [64][128] halves (stride 272B)
    {
        unsigned char* tile = sm;   // reuse SM_AHI region
        const int r0 = wM * 32 + (lane >> 2);
        const int c0 = wN * 32 + (lane & 3) * 2;
#pragma unroll
        for (int mt = 0; mt < 2; mt++)
#pragma unroll
            for (int nt = 0; nt < 4; nt++) {
                const int col = c0 + nt * 8;
                __half2 lo2 = __floats2half2_rn(acc[mt][nt][0], acc[mt][nt][1]);
                __half2 hi2 = __floats2half2_rn(acc[mt][nt][2], acc[mt][nt][3]);
                *(__half2*)(tile + (r0 + mt * 16)     * EPI_STR + col * 2) = lo2;
                *(__half2*)(tile + (r0 + mt * 16 + 8) * EPI_STR + col * 2) = hi2;
            }
    }
    __syncthreads();

    // Coalesced copy to g_Ph: 64 rows x 256B
    {
        const int rowm = tid >> 2;
        const int seg  = tid & 3;
        const int grow = rowBase + rowm;
        if (grow < N_NODES) {
            const uint4* s4 = (const uint4*)(sm + rowm * EPI_STR + seg * 64);
            uint4* d4 = (uint4*)((unsigned char*)g_Ph + (size_t)grow * 256 + seg * 64);
#pragma unroll
            for (int i = 0; i < 4; i++) d4[i] = s4[i];
        }
    }
}

// ---------------------------------------------------------------------------
// Edge kernel: 8 lanes per edge (4 edges/warp). u,v = 16B/lane, 128B coalesced.
// ---------------------------------------------------------------------------
__global__ __launch_bounds__(256) void edge_kernel(const int* __restrict__ row,
                                                   const int* __restrict__ col,
                                                   const float* __restrict__ W2,
                                                   const float* __restrict__ b2,
                                                   float* __restrict__ out) {
    const int gt  = blockIdx.x * 256 + threadIdx.x;
    const int e   = gt >> 3;
    const int sub = gt & 7;
    if (e >= N_EDGES) return;

    const int r = __ldg(row + e);
    const int c = __ldg(col + e);

    const uint4 ur = *(const uint4*)(g_Ph + (size_t)r * PDIM + sub * 8);
    const uint4 vr = *(const uint4*)(g_Ph + (size_t)c * PDIM + NHID + sub * 8);
    const float4 be0 = *(const float4*)(g_beff + sub * 8);
    const float4 be1 = *(const float4*)(g_beff + sub * 8 + 4);
    const float4 w0  = *(const float4*)(W2 + sub * 8);
    const float4 w1  = *(const float4*)(W2 + sub * 8 + 4);

    const __half2* uh = (const __half2*)&ur;
    const __half2* vh = (const __half2*)&vr;
    const float be[8] = {be0.x, be0.y, be0.z, be0.w, be1.x, be1.y, be1.z, be1.w};
    const float w[8]  = {w0.x,  w0.y,  w0.z,  w0.w,  w1.x,  w1.y,  w1.z,  w1.w};

    float acc = 0.f;
#pragma unroll
    for (int i = 0; i < 4; i++) {
        const float2 uf = __half22float2(uh[i]);
        const float2 vf = __half22float2(vh[i]);
        const float h0 = fmaxf(uf.x + vf.x + be[2 * i],     0.f);
        const float h1 = fmaxf(uf.y + vf.y + be[2 * i + 1], 0.f);
        acc = fmaf(h0, w[2 * i],     acc);
        acc = fmaf(h1, w[2 * i + 1], acc);
    }

#pragma unroll
    for (int o = 4; o; o >>= 1) acc += __shfl_xor_sync(0xffffffffu, acc, o, 8);

    if (sub == 0) out[e] = acc + __ldg(b2);
}

// ---------------------------------------------------------------------------
extern "C" void kernel_launch(void* const* d_in, const int* in_sizes, int n_in,
                              void* d_out, int out_size) {
    const float* seq   = (const float*)d_in[0];
    const float* W_enc = (const float*)d_in[1];
    const float* b_enc = (const float*)d_in[2];
    const float* W1    = (const float*)d_in[3];
    const float* b1    = (const float*)d_in[4];
    const float* W2    = (const float*)d_in[5];
    const float* b2    = (const float*)d_in[6];
    const int*   rowi  = (const int*)d_in[7];
    const int*   coli  = (const int*)d_in[8];
    float* out = (float*)d_out;

    prep_kernel<<<128, 128>>>(W_enc, W1, b_enc, b1);

    cudaFuncSetAttribute(gemm_kernel, cudaFuncAttributeMaxDynamicSharedMemorySize, SM_TOTAL);
    gemm_kernel<<<(N_NODES + 63) / 64, 256, SM_TOTAL>>>(seq);

    edge_kernel<<<(N_EDGES * 8 + 255) / 256, 256>>>(rowi, coli, W2, b2, out);
}